// round 2
// baseline (speedup 1.0000x reference)
#include <cuda_runtime.h>
#include <cuda_bf16.h>
#include <cstdint>

#define N_NODES_MAX 100000
#define FDIM 128

// ---------------- scratch (no allocs allowed) ----------------
__device__ float g_xt[(size_t)N_NODES_MAX * FDIM];   // x @ W for current layer
__device__ float g_h1[(size_t)N_NODES_MAX * FDIM];   // layer-1 output
__device__ float g_deg[N_NODES_MAX];
__device__ float g_dinv[N_NODES_MAX];

// ---------------- degree ----------------
__global__ void deg_init_kernel(float* deg, int n) {
    int i = blockIdx.x * blockDim.x + threadIdx.x;
    if (i < n) deg[i] = 1.0f;  // self-loop
}

__global__ void deg_scatter_kernel(const int* __restrict__ cols, float* deg, int E) {
    int i = blockIdx.x * blockDim.x + threadIdx.x;
    int stride = gridDim.x * blockDim.x;
    for (int e = i; e < E; e += stride) {
        int c = cols[e];
        atomicAdd(&deg[c], 1.0f);
    }
}

__global__ void dinv_kernel(const float* __restrict__ deg, float* dinv, int n) {
    int i = blockIdx.x * blockDim.x + threadIdx.x;
    if (i < n) dinv[i] = rsqrtf(deg[i]);
}

// ---------------- GEMM: out[N,128] = x[N,128] @ W[128,128] ----------------
// 128-row tile per block, full 128 cols, k-tiled by 32. 256 threads,
// each computes an 8x8 register tile (64 FMA per k per thread).
#define MT 128
#define KB 32

__global__ __launch_bounds__(256) void gemm_kernel(
    const float* __restrict__ x, const float* __restrict__ W,
    float* __restrict__ out, int nrows)
{
    __shared__ float xs[MT][KB + 4];   // padded to dodge bank conflicts
    __shared__ float ws[KB][FDIM];

    int tid = threadIdx.x;
    int tx = tid & 15;        // column group (8 cols)
    int ty = tid >> 4;        // row group (8 rows)
    int row0 = blockIdx.x * MT;

    float acc[8][8];
#pragma unroll
    for (int i = 0; i < 8; i++)
#pragma unroll
        for (int j = 0; j < 8; j++) acc[i][j] = 0.0f;

    int lr = tid >> 3;          // 0..31
    int lk = (tid & 7) * 4;     // 0..28
    int wk = tid >> 5;          // 0..7
    int wc = (tid & 31) * 4;    // 0..124

    for (int k0 = 0; k0 < FDIM; k0 += KB) {
        // x tile: 128 rows x 32 k
#pragma unroll
        for (int p = 0; p < 4; p++) {
            int r = lr + p * 32;
            float4 v = make_float4(0.f, 0.f, 0.f, 0.f);
            if (row0 + r < nrows)
                v = *(const float4*)(x + (long long)(row0 + r) * FDIM + k0 + lk);
            *(float4*)(&xs[r][lk]) = v;
        }
        // W tile: 32 k x 128 cols
#pragma unroll
        for (int p = 0; p < 4; p++) {
            int kk = wk + p * 8;
            float4 v = *(const float4*)(W + (long long)(k0 + kk) * FDIM + wc);
            *(float4*)(&ws[kk][wc]) = v;
        }
        __syncthreads();

#pragma unroll
        for (int kk = 0; kk < KB; kk++) {
            float xf[8], wf[8];
#pragma unroll
            for (int i = 0; i < 8; i++) xf[i] = xs[ty * 8 + i][kk];
            float4 w0 = *(float4*)(&ws[kk][tx * 8]);
            float4 w1 = *(float4*)(&ws[kk][tx * 8 + 4]);
            wf[0] = w0.x; wf[1] = w0.y; wf[2] = w0.z; wf[3] = w0.w;
            wf[4] = w1.x; wf[5] = w1.y; wf[6] = w1.z; wf[7] = w1.w;
#pragma unroll
            for (int i = 0; i < 8; i++)
#pragma unroll
                for (int j = 0; j < 8; j++)
                    acc[i][j] = fmaf(xf[i], wf[j], acc[i][j]);
        }
        __syncthreads();
    }

#pragma unroll
    for (int i = 0; i < 8; i++) {
        int r = row0 + ty * 8 + i;
        if (r < nrows) {
            float4 o0 = make_float4(acc[i][0], acc[i][1], acc[i][2], acc[i][3]);
            float4 o1 = make_float4(acc[i][4], acc[i][5], acc[i][6], acc[i][7]);
            *(float4*)(out + (long long)r * FDIM + tx * 8)     = o0;
            *(float4*)(out + (long long)r * FDIM + tx * 8 + 4) = o1;
        }
    }
}

// ---------------- node init: out = xt * dinv^2 + b ----------------
__global__ void node_init_kernel(
    const float* __restrict__ xt, const float* __restrict__ dinv,
    const float* __restrict__ b, float* __restrict__ out, int n)
{
    int i = blockIdx.x * blockDim.x + threadIdx.x;  // float4 index
    int total = n * (FDIM / 4);
    if (i < total) {
        int node = i >> 5;          // 32 float4 per node
        int j4 = (i & 31) * 4;
        float s = dinv[node];
        s = s * s;
        float4 v  = *(const float4*)(xt + (long long)i * 4);
        float4 bb = *(const float4*)(b + j4);
        v.x = fmaf(v.x, s, bb.x);
        v.y = fmaf(v.y, s, bb.y);
        v.z = fmaf(v.z, s, bb.z);
        v.w = fmaf(v.w, s, bb.w);
        *(float4*)(out + (long long)i * 4) = v;
    }
}

// ---------------- edge scatter: out[col] += xt[row] * dinv[row]*dinv[col] ----------------
// One warp per edge; each lane handles 4 floats with a vector reduction.
__global__ __launch_bounds__(256) void edge_scatter_kernel(
    const int* __restrict__ rows, const int* __restrict__ cols,
    const float* __restrict__ xt, const float* __restrict__ dinv,
    float* out, int E)
{
    int gwarp = (blockIdx.x * blockDim.x + threadIdx.x) >> 5;
    int lane = threadIdx.x & 31;
    int nw = (gridDim.x * blockDim.x) >> 5;
    for (int e = gwarp; e < E; e += nw) {
        int r = __ldg(rows + e);
        int c = __ldg(cols + e);
        float norm = __ldg(dinv + r) * __ldg(dinv + c);
        float4 v = *(const float4*)(xt + (long long)r * FDIM + lane * 4);
        float a0 = v.x * norm, a1 = v.y * norm, a2 = v.z * norm, a3 = v.w * norm;
        float* dst = out + (long long)c * FDIM + lane * 4;
        asm volatile("red.global.add.v4.f32 [%0], {%1, %2, %3, %4};"
                     :: "l"(dst), "f"(a0), "f"(a1), "f"(a2), "f"(a3)
                     : "memory");
    }
}

// ---------------- launch ----------------
extern "C" void kernel_launch(void* const* d_in, const int* in_sizes, int n_in,
                              void* d_out, int out_size)
{
    const float* node_feature = (const float*)d_in[0];
    const int*   edge_index   = (const int*)d_in[1];   // int32! (jax x64 disabled)
    const float* W1 = (const float*)d_in[2];
    const float* b1 = (const float*)d_in[3];
    const float* W2 = (const float*)d_in[4];
    const float* b2 = (const float*)d_in[5];
    float* out = (float*)d_out;

    int n = in_sizes[0] / FDIM;          // 100000
    int E = in_sizes[1] / 2;             // 1600000
    const int* rows = edge_index;
    const int* cols = edge_index + E;

    float *xt, *h1, *deg, *dinv;
    cudaGetSymbolAddress((void**)&xt,   g_xt);
    cudaGetSymbolAddress((void**)&h1,   g_h1);
    cudaGetSymbolAddress((void**)&deg,  g_deg);
    cudaGetSymbolAddress((void**)&dinv, g_dinv);

    int tb = 256;
    int nb_nodes   = (n + tb - 1) / tb;
    int nb_edges   = (E + tb - 1) / tb;
    int nb_gemm    = (n + MT - 1) / MT;
    int nb_ninit   = (n * (FDIM / 4) + tb - 1) / tb;
    long long nwarp_threads = (long long)E * 32;
    int nb_scatter = (int)((nwarp_threads + tb - 1) / tb);

    // degree + dinv (shared by both layers)
    deg_init_kernel<<<nb_nodes, tb>>>(deg, n);
    deg_scatter_kernel<<<nb_edges, tb>>>(cols, deg, E);
    dinv_kernel<<<nb_nodes, tb>>>(deg, dinv, n);

    // layer 1: h1 = scatter(x@W1) + self + b1
    gemm_kernel<<<nb_gemm, tb>>>(node_feature, W1, xt, n);
    node_init_kernel<<<nb_ninit, tb>>>(xt, dinv, b1, h1, n);
    edge_scatter_kernel<<<nb_scatter, tb>>>(rows, cols, xt, dinv, h1, E);

    // layer 2: out = scatter(h1@W2) + self + b2
    gemm_kernel<<<nb_gemm, tb>>>(h1, W2, xt, n);
    node_init_kernel<<<nb_ninit, tb>>>(xt, dinv, b2, out, n);
    edge_scatter_kernel<<<nb_scatter, tb>>>(rows, cols, xt, dinv, out, E);
}

// round 3
// speedup vs baseline: 1.9960x; 1.9960x over previous
#include <cuda_runtime.h>
#include <cuda_bf16.h>
#include <cstdint>

#define N_NODES_MAX 100000
#define N_EDGES_MAX 1600000
#define FDIM 128
#define SCAN_BS 512

// ---------------- scratch (no allocs allowed) ----------------
__device__ float g_xt[(size_t)N_NODES_MAX * FDIM];   // x @ W for current layer
__device__ float g_h1[(size_t)N_NODES_MAX * FDIM];   // layer-1 output
__device__ float g_dinv[N_NODES_MAX];
__device__ int   g_cnt[N_NODES_MAX];                 // in-degree (excl self-loop)
__device__ int   g_rowptr[N_NODES_MAX];              // exclusive scan of cnt
__device__ int   g_cur[N_NODES_MAX];                 // placement cursors
__device__ int   g_src_sorted[N_EDGES_MAX];          // src ids grouped by dst
__device__ int   g_bsums[512];                       // scan block sums

// ---------------- histogram + dinv ----------------
__global__ void cnt_zero_kernel(int* cnt, int n) {
    int i = blockIdx.x * blockDim.x + threadIdx.x;
    if (i < n) cnt[i] = 0;
}

__global__ void hist_kernel(const int* __restrict__ cols, int* cnt, int E) {
    int i = blockIdx.x * blockDim.x + threadIdx.x;
    int stride = gridDim.x * blockDim.x;
    for (int e = i; e < E; e += stride) atomicAdd(&cnt[cols[e]], 1);
}

__global__ void dinv_kernel(const int* __restrict__ cnt, float* dinv, int n) {
    int i = blockIdx.x * blockDim.x + threadIdx.x;
    if (i < n) dinv[i] = rsqrtf((float)cnt[i] + 1.0f);  // +1 self-loop
}

// ---------------- exclusive scan (3 kernels) ----------------
__global__ void scan_block_kernel(const int* __restrict__ cnt, int* scanout,
                                  int* bsums, int n) {
    __shared__ int sh[SCAN_BS];
    int gid = blockIdx.x * SCAN_BS + threadIdx.x;
    int v = (gid < n) ? cnt[gid] : 0;
    sh[threadIdx.x] = v;
    __syncthreads();
    for (int off = 1; off < SCAN_BS; off <<= 1) {
        int t = (threadIdx.x >= off) ? sh[threadIdx.x - off] : 0;
        __syncthreads();
        sh[threadIdx.x] += t;
        __syncthreads();
    }
    if (gid < n) scanout[gid] = sh[threadIdx.x] - v;  // exclusive
    if (threadIdx.x == SCAN_BS - 1) bsums[blockIdx.x] = sh[threadIdx.x];
}

__global__ void scan_sums_kernel(int* bsums, int nb) {
    __shared__ int sh[SCAN_BS];
    int v = (threadIdx.x < nb) ? bsums[threadIdx.x] : 0;
    sh[threadIdx.x] = v;
    __syncthreads();
    for (int off = 1; off < SCAN_BS; off <<= 1) {
        int t = (threadIdx.x >= off) ? sh[threadIdx.x - off] : 0;
        __syncthreads();
        sh[threadIdx.x] += t;
        __syncthreads();
    }
    if (threadIdx.x < nb) bsums[threadIdx.x] = sh[threadIdx.x] - v;  // exclusive
}

__global__ void scan_add_cursor_kernel(int* scanout, const int* __restrict__ bsums,
                                       int* cur, int n) {
    int gid = blockIdx.x * SCAN_BS + threadIdx.x;
    if (gid < n) {
        int v = scanout[gid] + bsums[blockIdx.x];
        scanout[gid] = v;
        cur[gid] = v;
    }
}

// ---------------- edge placement (counting sort by dst) ----------------
__global__ void place_kernel(const int* __restrict__ rows, const int* __restrict__ cols,
                             int* cur, int* __restrict__ srcs, int E) {
    int i = blockIdx.x * blockDim.x + threadIdx.x;
    int stride = gridDim.x * blockDim.x;
    for (int e = i; e < E; e += stride) {
        int c = cols[e];
        int p = atomicAdd(&cur[c], 1);
        srcs[p] = rows[e];
    }
}

// ---------------- GEMM: out[N,128] = x[N,128] @ W[128,128] ----------------
#define MT 128
#define KB 32

__global__ __launch_bounds__(256, 2) void gemm_kernel(
    const float* __restrict__ x, const float* __restrict__ W,
    float* __restrict__ out, int nrows)
{
    __shared__ float xs[MT][KB + 4];
    __shared__ float ws[KB][FDIM];

    int tid = threadIdx.x;
    int tx = tid & 15;
    int ty = tid >> 4;
    int row0 = blockIdx.x * MT;

    float acc[8][8];
#pragma unroll
    for (int i = 0; i < 8; i++)
#pragma unroll
        for (int j = 0; j < 8; j++) acc[i][j] = 0.0f;

    int lr = tid >> 3;
    int lk = (tid & 7) * 4;
    int wk = tid >> 5;
    int wc = (tid & 31) * 4;

    for (int k0 = 0; k0 < FDIM; k0 += KB) {
#pragma unroll
        for (int p = 0; p < 4; p++) {
            int r = lr + p * 32;
            float4 v = make_float4(0.f, 0.f, 0.f, 0.f);
            if (row0 + r < nrows)
                v = *(const float4*)(x + (long long)(row0 + r) * FDIM + k0 + lk);
            *(float4*)(&xs[r][lk]) = v;
        }
#pragma unroll
        for (int p = 0; p < 4; p++) {
            int kk = wk + p * 8;
            float4 v = *(const float4*)(W + (long long)(k0 + kk) * FDIM + wc);
            *(float4*)(&ws[kk][wc]) = v;
        }
        __syncthreads();

#pragma unroll
        for (int kk = 0; kk < KB; kk++) {
            float xf[8], wf[8];
#pragma unroll
            for (int i = 0; i < 8; i++) xf[i] = xs[ty * 8 + i][kk];
            float4 w0 = *(float4*)(&ws[kk][tx * 8]);
            float4 w1 = *(float4*)(&ws[kk][tx * 8 + 4]);
            wf[0] = w0.x; wf[1] = w0.y; wf[2] = w0.z; wf[3] = w0.w;
            wf[4] = w1.x; wf[5] = w1.y; wf[6] = w1.z; wf[7] = w1.w;
#pragma unroll
            for (int i = 0; i < 8; i++)
#pragma unroll
                for (int j = 0; j < 8; j++)
                    acc[i][j] = fmaf(xf[i], wf[j], acc[i][j]);
        }
        __syncthreads();
    }

#pragma unroll
    for (int i = 0; i < 8; i++) {
        int r = row0 + ty * 8 + i;
        if (r < nrows) {
            float4 o0 = make_float4(acc[i][0], acc[i][1], acc[i][2], acc[i][3]);
            float4 o1 = make_float4(acc[i][4], acc[i][5], acc[i][6], acc[i][7]);
            *(float4*)(out + (long long)r * FDIM + tx * 8)     = o0;
            *(float4*)(out + (long long)r * FDIM + tx * 8 + 4) = o1;
        }
    }
}

// ---------------- aggregate: one warp per destination node ----------------
// out[d] = b + xt[d]*dinv[d]^2 + sum_{s in in(d)} xt[s]*dinv[s]*dinv[d]
__global__ __launch_bounds__(256) void aggregate_kernel(
    const float* __restrict__ xt, const int* __restrict__ rowptr,
    const int* __restrict__ cnt, const int* __restrict__ srcs,
    const float* __restrict__ dinv, const float* __restrict__ b,
    float* __restrict__ out, int n)
{
    int warp = (blockIdx.x * blockDim.x + threadIdx.x) >> 5;
    int lane = threadIdx.x & 31;
    if (warp >= n) return;

    float dc = __ldg(dinv + warp);
    float4 bb = *(const float4*)(b + lane * 4);
    float4 sv = *(const float4*)(xt + (long long)warp * FDIM + lane * 4);
    float self = dc * dc;
    float4 acc;
    acc.x = fmaf(sv.x, self, bb.x);
    acc.y = fmaf(sv.y, self, bb.y);
    acc.z = fmaf(sv.z, self, bb.z);
    acc.w = fmaf(sv.w, self, bb.w);

    int k0 = __ldg(rowptr + warp);
    int k1 = k0 + __ldg(cnt + warp);
#pragma unroll 2
    for (int k = k0; k < k1; k++) {
        int s = __ldg(srcs + k);
        float norm = dc * __ldg(dinv + s);
        float4 v = *(const float4*)(xt + (long long)s * FDIM + lane * 4);
        acc.x = fmaf(v.x, norm, acc.x);
        acc.y = fmaf(v.y, norm, acc.y);
        acc.z = fmaf(v.z, norm, acc.z);
        acc.w = fmaf(v.w, norm, acc.w);
    }
    *(float4*)(out + (long long)warp * FDIM + lane * 4) = acc;
}

// ---------------- launch ----------------
extern "C" void kernel_launch(void* const* d_in, const int* in_sizes, int n_in,
                              void* d_out, int out_size)
{
    const float* node_feature = (const float*)d_in[0];
    const int*   edge_index   = (const int*)d_in[1];   // int32 (jax x64 disabled)
    const float* W1 = (const float*)d_in[2];
    const float* b1 = (const float*)d_in[3];
    const float* W2 = (const float*)d_in[4];
    const float* b2 = (const float*)d_in[5];
    float* out = (float*)d_out;

    int n = in_sizes[0] / FDIM;          // 100000
    int E = in_sizes[1] / 2;             // 1600000
    const int* rows = edge_index;
    const int* cols = edge_index + E;

    float *xt, *h1, *dinv;
    int *cnt, *rowptr, *cur, *srcs, *bsums;
    cudaGetSymbolAddress((void**)&xt,     g_xt);
    cudaGetSymbolAddress((void**)&h1,     g_h1);
    cudaGetSymbolAddress((void**)&dinv,   g_dinv);
    cudaGetSymbolAddress((void**)&cnt,    g_cnt);
    cudaGetSymbolAddress((void**)&rowptr, g_rowptr);
    cudaGetSymbolAddress((void**)&cur,    g_cur);
    cudaGetSymbolAddress((void**)&srcs,   g_src_sorted);
    cudaGetSymbolAddress((void**)&bsums,  g_bsums);

    int tb = 256;
    int nb_nodes = (n + tb - 1) / tb;
    int nb_edges = (E + tb - 1) / tb;
    int nb_gemm  = (n + MT - 1) / MT;
    int nb_scan  = (n + SCAN_BS - 1) / SCAN_BS;   // 196
    int nb_agg   = (n * 32 + tb - 1) / tb;        // one warp per node

    // CSR build (shared by both layers)
    cnt_zero_kernel<<<nb_nodes, tb>>>(cnt, n);
    hist_kernel<<<nb_edges, tb>>>(cols, cnt, E);
    dinv_kernel<<<nb_nodes, tb>>>(cnt, dinv, n);
    scan_block_kernel<<<nb_scan, SCAN_BS>>>(cnt, rowptr, bsums, n);
    scan_sums_kernel<<<1, SCAN_BS>>>(bsums, nb_scan);
    scan_add_cursor_kernel<<<nb_scan, SCAN_BS>>>(rowptr, bsums, cur, n);
    place_kernel<<<nb_edges, tb>>>(rows, cols, cur, srcs, E);

    // layer 1
    gemm_kernel<<<nb_gemm, tb>>>(node_feature, W1, xt, n);
    aggregate_kernel<<<nb_agg, tb>>>(xt, rowptr, cnt, srcs, dinv, b1, h1, n);

    // layer 2
    gemm_kernel<<<nb_gemm, tb>>>(h1, W2, xt, n);
    aggregate_kernel<<<nb_agg, tb>>>(xt, rowptr, cnt, srcs, dinv, b2, out, n);
}

// round 4
// speedup vs baseline: 3.0947x; 1.5504x over previous
#include <cuda_runtime.h>
#include <cuda_bf16.h>
#include <cstdint>

#define N_NODES_MAX 100000
#define N_EDGES_MAX 1600000
#define FDIM 128
#define SCAN_BS 512

// ---------------- scratch (no allocs allowed) ----------------
__device__ float g_xt[(size_t)N_NODES_MAX * FDIM];
__device__ float g_h1[(size_t)N_NODES_MAX * FDIM];
__device__ float g_dinv[N_NODES_MAX];
__device__ int   g_cnt[N_NODES_MAX];
__device__ int   g_rowptr[N_NODES_MAX];
__device__ int   g_cur[N_NODES_MAX];
__device__ int   g_src_sorted[N_EDGES_MAX];
__device__ int   g_bsums[512];

// ---------------- histogram + dinv ----------------
__global__ void cnt_zero_kernel(int* cnt, int n) {
    int i = blockIdx.x * blockDim.x + threadIdx.x;
    if (i < n) cnt[i] = 0;
}

__global__ void hist_kernel(const int* __restrict__ cols, int* cnt, int E) {
    int i = blockIdx.x * blockDim.x + threadIdx.x;
    int stride = gridDim.x * blockDim.x;
    int E4 = E >> 2;
    const int4* c4 = (const int4*)cols;
    for (int e = i; e < E4; e += stride) {
        int4 v = c4[e];
        atomicAdd(&cnt[v.x], 1);
        atomicAdd(&cnt[v.y], 1);
        atomicAdd(&cnt[v.z], 1);
        atomicAdd(&cnt[v.w], 1);
    }
    for (int e = E4 * 4 + i; e < E; e += stride) atomicAdd(&cnt[cols[e]], 1);
}

__global__ void dinv_kernel(const int* __restrict__ cnt, float* dinv, int n) {
    int i = blockIdx.x * blockDim.x + threadIdx.x;
    if (i < n) dinv[i] = rsqrtf((float)cnt[i] + 1.0f);
}

// ---------------- exclusive scan (3 kernels) ----------------
__global__ void scan_block_kernel(const int* __restrict__ cnt, int* scanout,
                                  int* bsums, int n) {
    __shared__ int sh[SCAN_BS];
    int gid = blockIdx.x * SCAN_BS + threadIdx.x;
    int v = (gid < n) ? cnt[gid] : 0;
    sh[threadIdx.x] = v;
    __syncthreads();
    for (int off = 1; off < SCAN_BS; off <<= 1) {
        int t = (threadIdx.x >= off) ? sh[threadIdx.x - off] : 0;
        __syncthreads();
        sh[threadIdx.x] += t;
        __syncthreads();
    }
    if (gid < n) scanout[gid] = sh[threadIdx.x] - v;
    if (threadIdx.x == SCAN_BS - 1) bsums[blockIdx.x] = sh[threadIdx.x];
}

__global__ void scan_sums_kernel(int* bsums, int nb) {
    __shared__ int sh[SCAN_BS];
    int v = (threadIdx.x < nb) ? bsums[threadIdx.x] : 0;
    sh[threadIdx.x] = v;
    __syncthreads();
    for (int off = 1; off < SCAN_BS; off <<= 1) {
        int t = (threadIdx.x >= off) ? sh[threadIdx.x - off] : 0;
        __syncthreads();
        sh[threadIdx.x] += t;
        __syncthreads();
    }
    if (threadIdx.x < nb) bsums[threadIdx.x] = sh[threadIdx.x] - v;
}

__global__ void scan_add_cursor_kernel(int* scanout, const int* __restrict__ bsums,
                                       int* cur, int n) {
    int gid = blockIdx.x * SCAN_BS + threadIdx.x;
    if (gid < n) {
        int v = scanout[gid] + bsums[blockIdx.x];
        scanout[gid] = v;
        cur[gid] = v;
    }
}

// ---------------- edge placement (counting sort by dst) ----------------
__global__ void place_kernel(const int* __restrict__ rows, const int* __restrict__ cols,
                             int* cur, int* __restrict__ srcs, int E) {
    int i = blockIdx.x * blockDim.x + threadIdx.x;
    int stride = gridDim.x * blockDim.x;
    int E4 = E >> 2;
    const int4* r4 = (const int4*)rows;
    const int4* c4 = (const int4*)cols;
    for (int e = i; e < E4; e += stride) {
        int4 c = c4[e];
        int4 r = r4[e];
        srcs[atomicAdd(&cur[c.x], 1)] = r.x;
        srcs[atomicAdd(&cur[c.y], 1)] = r.y;
        srcs[atomicAdd(&cur[c.z], 1)] = r.z;
        srcs[atomicAdd(&cur[c.w], 1)] = r.w;
    }
    for (int e = E4 * 4 + i; e < E; e += stride)
        srcs[atomicAdd(&cur[cols[e]], 1)] = rows[e];
}

// ---------------- tf32 tensor-core GEMM: out[N,128] = x[N,128] @ W[128,128] ----
#define MT 128
#define KB 32

__device__ __forceinline__ uint32_t f2tf32(float f) {
    uint32_t u;
    asm("cvt.rna.tf32.f32 %0, %1;" : "=r"(u) : "f"(f));
    return u;
}

__global__ __launch_bounds__(256, 2) void gemm_tc_kernel(
    const float* __restrict__ x, const float* __restrict__ W,
    float* __restrict__ out, int nrows)
{
    __shared__ uint32_t xs[MT][KB + 4];     // tf32-rounded; stride 36 -> conflict-free frags
    __shared__ uint32_t ws[KB][FDIM + 8];   // tf32-rounded; stride 136 -> conflict-free frags

    int tid = threadIdx.x;
    int wid = tid >> 5;
    int lane = tid & 31;
    int m_base = (wid & 3) * 32;    // warp m offset
    int n_base = (wid >> 2) * 64;   // warp n offset
    int row0 = blockIdx.x * MT;

    float acc[2][8][4];
#pragma unroll
    for (int im = 0; im < 2; im++)
#pragma unroll
        for (int in = 0; in < 8; in++)
#pragma unroll
            for (int j = 0; j < 4; j++) acc[im][in][j] = 0.0f;

    int lr = tid >> 3;          // 0..31
    int lk = (tid & 7) * 4;     // 0..28
    int wk = tid >> 5;          // 0..7
    int wc = (tid & 31) * 4;    // 0..124

    for (int k0 = 0; k0 < FDIM; k0 += KB) {
        // x tile: 128 rows x 32 k (tf32-rounded)
#pragma unroll
        for (int p = 0; p < 4; p++) {
            int r = lr + p * 32;
            float4 v = make_float4(0.f, 0.f, 0.f, 0.f);
            if (row0 + r < nrows)
                v = *(const float4*)(x + (long long)(row0 + r) * FDIM + k0 + lk);
            xs[r][lk]     = f2tf32(v.x);
            xs[r][lk + 1] = f2tf32(v.y);
            xs[r][lk + 2] = f2tf32(v.z);
            xs[r][lk + 3] = f2tf32(v.w);
        }
        // W tile: 32 k x 128 cols
#pragma unroll
        for (int p = 0; p < 4; p++) {
            int kk = wk + p * 8;
            float4 v = *(const float4*)(W + (long long)(k0 + kk) * FDIM + wc);
            ws[kk][wc]     = f2tf32(v.x);
            ws[kk][wc + 1] = f2tf32(v.y);
            ws[kk][wc + 2] = f2tf32(v.z);
            ws[kk][wc + 3] = f2tf32(v.w);
        }
        __syncthreads();

#pragma unroll
        for (int ks = 0; ks < KB / 8; ks++) {
            int kk = ks * 8;
            uint32_t a[2][4];
            int ac = kk + (lane & 3);
#pragma unroll
            for (int im = 0; im < 2; im++) {
                int r0 = m_base + im * 16 + (lane >> 2);
                a[im][0] = xs[r0][ac];
                a[im][1] = xs[r0 + 8][ac];
                a[im][2] = xs[r0][ac + 4];
                a[im][3] = xs[r0 + 8][ac + 4];
            }
#pragma unroll
            for (int in = 0; in < 8; in++) {
                int c = n_base + in * 8 + (lane >> 2);
                uint32_t b0 = ws[kk + (lane & 3)][c];
                uint32_t b1 = ws[kk + 4 + (lane & 3)][c];
#pragma unroll
                for (int im = 0; im < 2; im++) {
                    asm volatile(
                        "mma.sync.aligned.m16n8k8.row.col.f32.tf32.tf32.f32 "
                        "{%0,%1,%2,%3}, {%4,%5,%6,%7}, {%8,%9}, {%0,%1,%2,%3};"
                        : "+f"(acc[im][in][0]), "+f"(acc[im][in][1]),
                          "+f"(acc[im][in][2]), "+f"(acc[im][in][3])
                        : "r"(a[im][0]), "r"(a[im][1]), "r"(a[im][2]), "r"(a[im][3]),
                          "r"(b0), "r"(b1));
                }
            }
        }
        __syncthreads();
    }

    // epilogue: C layout c0/c1 -> (row, 2*(lane&3)+{0,1}), c2/c3 -> row+8
#pragma unroll
    for (int im = 0; im < 2; im++) {
        int r = row0 + m_base + im * 16 + (lane >> 2);
#pragma unroll
        for (int in = 0; in < 8; in++) {
            int c = n_base + in * 8 + 2 * (lane & 3);
            if (r < nrows)
                *(float2*)(out + (long long)r * FDIM + c) =
                    make_float2(acc[im][in][0], acc[im][in][1]);
            if (r + 8 < nrows)
                *(float2*)(out + (long long)(r + 8) * FDIM + c) =
                    make_float2(acc[im][in][2], acc[im][in][3]);
        }
    }
}

// ---------------- aggregate: one warp per destination node ----------------
__global__ __launch_bounds__(256) void aggregate_kernel(
    const float* __restrict__ xt, const int* __restrict__ rowptr,
    const int* __restrict__ cnt, const int* __restrict__ srcs,
    const float* __restrict__ dinv, const float* __restrict__ b,
    float* __restrict__ out, int n)
{
    int warp = (blockIdx.x * blockDim.x + threadIdx.x) >> 5;
    int lane = threadIdx.x & 31;
    if (warp >= n) return;

    float dc = __ldg(dinv + warp);
    float4 bb = *(const float4*)(b + lane * 4);
    float4 sv = *(const float4*)(xt + (long long)warp * FDIM + lane * 4);
    float self = dc * dc;
    float4 acc;
    acc.x = fmaf(sv.x, self, bb.x);
    acc.y = fmaf(sv.y, self, bb.y);
    acc.z = fmaf(sv.z, self, bb.z);
    acc.w = fmaf(sv.w, self, bb.w);

    int k0 = __ldg(rowptr + warp);
    int k1 = k0 + __ldg(cnt + warp);
#pragma unroll 2
    for (int k = k0; k < k1; k++) {
        int s = __ldg(srcs + k);
        float norm = dc * __ldg(dinv + s);
        float4 v = *(const float4*)(xt + (long long)s * FDIM + lane * 4);
        acc.x = fmaf(v.x, norm, acc.x);
        acc.y = fmaf(v.y, norm, acc.y);
        acc.z = fmaf(v.z, norm, acc.z);
        acc.w = fmaf(v.w, norm, acc.w);
    }
    *(float4*)(out + (long long)warp * FDIM + lane * 4) = acc;
}

// ---------------- launch ----------------
extern "C" void kernel_launch(void* const* d_in, const int* in_sizes, int n_in,
                              void* d_out, int out_size)
{
    const float* node_feature = (const float*)d_in[0];
    const int*   edge_index   = (const int*)d_in[1];   // int32 (jax x64 disabled)
    const float* W1 = (const float*)d_in[2];
    const float* b1 = (const float*)d_in[3];
    const float* W2 = (const float*)d_in[4];
    const float* b2 = (const float*)d_in[5];
    float* out = (float*)d_out;

    int n = in_sizes[0] / FDIM;          // 100000
    int E = in_sizes[1] / 2;             // 1600000
    const int* rows = edge_index;
    const int* cols = edge_index + E;

    float *xt, *h1, *dinv;
    int *cnt, *rowptr, *cur, *srcs, *bsums;
    cudaGetSymbolAddress((void**)&xt,     g_xt);
    cudaGetSymbolAddress((void**)&h1,     g_h1);
    cudaGetSymbolAddress((void**)&dinv,   g_dinv);
    cudaGetSymbolAddress((void**)&cnt,    g_cnt);
    cudaGetSymbolAddress((void**)&rowptr, g_rowptr);
    cudaGetSymbolAddress((void**)&cur,    g_cur);
    cudaGetSymbolAddress((void**)&srcs,   g_src_sorted);
    cudaGetSymbolAddress((void**)&bsums,  g_bsums);

    int tb = 256;
    int nb_nodes = (n + tb - 1) / tb;
    int nb_edge4 = ((E >> 2) + tb - 1) / tb;
    int nb_gemm  = (n + MT - 1) / MT;
    int nb_scan  = (n + SCAN_BS - 1) / SCAN_BS;
    int nb_agg   = (n * 32 + tb - 1) / tb;

    // CSR build (shared by both layers)
    cnt_zero_kernel<<<nb_nodes, tb>>>(cnt, n);
    hist_kernel<<<nb_edge4, tb>>>(cols, cnt, E);
    dinv_kernel<<<nb_nodes, tb>>>(cnt, dinv, n);
    scan_block_kernel<<<nb_scan, SCAN_BS>>>(cnt, rowptr, bsums, n);
    scan_sums_kernel<<<1, SCAN_BS>>>(bsums, nb_scan);
    scan_add_cursor_kernel<<<nb_scan, SCAN_BS>>>(rowptr, bsums, cur, n);
    place_kernel<<<nb_edge4, tb>>>(rows, cols, cur, srcs, E);

    // layer 1
    gemm_tc_kernel<<<nb_gemm, tb>>>(node_feature, W1, xt, n);
    aggregate_kernel<<<nb_agg, tb>>>(xt, rowptr, cnt, srcs, dinv, b1, h1, n);

    // layer 2
    gemm_tc_kernel<<<nb_gemm, tb>>>(h1, W2, xt, n);
    aggregate_kernel<<<nb_agg, tb>>>(xt, rowptr, cnt, srcs, dinv, b2, out, n);
}

// round 5
// speedup vs baseline: 3.3741x; 1.0903x over previous
#include <cuda_runtime.h>
#include <cuda_fp16.h>
#include <cstdint>

#define N_NODES_MAX 100000
#define N_EDGES_MAX 1600000
#define FDIM 128
#define SCAN_BS 512

// ---------------- scratch (no allocs allowed) ----------------
__device__ __half g_xt[(size_t)N_NODES_MAX * FDIM];   // GEMM output, fp16
__device__ float  g_h1[(size_t)N_NODES_MAX * FDIM];   // layer-1 output, fp32
__device__ float  g_dinv[N_NODES_MAX];
__device__ int    g_cnt[N_NODES_MAX];
__device__ int    g_rowptr[N_NODES_MAX];
__device__ int    g_cur[N_NODES_MAX];
__device__ int    g_src_sorted[N_EDGES_MAX];
__device__ int    g_bsums[512];

// ---------------- histogram + dinv ----------------
__global__ void cnt_zero_kernel(int* cnt, int n) {
    int i = blockIdx.x * blockDim.x + threadIdx.x;
    if (i < n) cnt[i] = 0;
}

__global__ void hist_kernel(const int* __restrict__ cols, int* cnt, int E) {
    int i = blockIdx.x * blockDim.x + threadIdx.x;
    int stride = gridDim.x * blockDim.x;
    int E4 = E >> 2;
    const int4* c4 = (const int4*)cols;
    for (int e = i; e < E4; e += stride) {
        int4 v = c4[e];
        atomicAdd(&cnt[v.x], 1);
        atomicAdd(&cnt[v.y], 1);
        atomicAdd(&cnt[v.z], 1);
        atomicAdd(&cnt[v.w], 1);
    }
    for (int e = E4 * 4 + i; e < E; e += stride) atomicAdd(&cnt[cols[e]], 1);
}

__global__ void dinv_kernel(const int* __restrict__ cnt, float* dinv, int n) {
    int i = blockIdx.x * blockDim.x + threadIdx.x;
    if (i < n) dinv[i] = rsqrtf((float)cnt[i] + 1.0f);
}

// ---------------- exclusive scan (3 kernels) ----------------
__global__ void scan_block_kernel(const int* __restrict__ cnt, int* scanout,
                                  int* bsums, int n) {
    __shared__ int sh[SCAN_BS];
    int gid = blockIdx.x * SCAN_BS + threadIdx.x;
    int v = (gid < n) ? cnt[gid] : 0;
    sh[threadIdx.x] = v;
    __syncthreads();
    for (int off = 1; off < SCAN_BS; off <<= 1) {
        int t = (threadIdx.x >= off) ? sh[threadIdx.x - off] : 0;
        __syncthreads();
        sh[threadIdx.x] += t;
        __syncthreads();
    }
    if (gid < n) scanout[gid] = sh[threadIdx.x] - v;
    if (threadIdx.x == SCAN_BS - 1) bsums[blockIdx.x] = sh[threadIdx.x];
}

__global__ void scan_sums_kernel(int* bsums, int nb) {
    __shared__ int sh[SCAN_BS];
    int v = (threadIdx.x < nb) ? bsums[threadIdx.x] : 0;
    sh[threadIdx.x] = v;
    __syncthreads();
    for (int off = 1; off < SCAN_BS; off <<= 1) {
        int t = (threadIdx.x >= off) ? sh[threadIdx.x - off] : 0;
        __syncthreads();
        sh[threadIdx.x] += t;
        __syncthreads();
    }
    if (threadIdx.x < nb) bsums[threadIdx.x] = sh[threadIdx.x] - v;
}

__global__ void scan_add_cursor_kernel(int* scanout, const int* __restrict__ bsums,
                                       int* cur, int n) {
    int gid = blockIdx.x * SCAN_BS + threadIdx.x;
    if (gid < n) {
        int v = scanout[gid] + bsums[blockIdx.x];
        scanout[gid] = v;
        cur[gid] = v;
    }
}

// ---------------- edge placement (counting sort by dst) ----------------
__global__ void place_kernel(const int* __restrict__ rows, const int* __restrict__ cols,
                             int* cur, int* __restrict__ srcs, int E) {
    int i = blockIdx.x * blockDim.x + threadIdx.x;
    int stride = gridDim.x * blockDim.x;
    int E4 = E >> 2;
    const int4* r4 = (const int4*)rows;
    const int4* c4 = (const int4*)cols;
    for (int e = i; e < E4; e += stride) {
        int4 c = c4[e];
        int4 r = r4[e];
        srcs[atomicAdd(&cur[c.x], 1)] = r.x;
        srcs[atomicAdd(&cur[c.y], 1)] = r.y;
        srcs[atomicAdd(&cur[c.z], 1)] = r.z;
        srcs[atomicAdd(&cur[c.w], 1)] = r.w;
    }
    for (int e = E4 * 4 + i; e < E; e += stride)
        srcs[atomicAdd(&cur[cols[e]], 1)] = rows[e];
}

// ---------------- tf32 tensor-core GEMM: out_h[N,128] = x[N,128] @ W[128,128] ----
#define MT 128
#define KB 32

__device__ __forceinline__ uint32_t f2tf32(float f) {
    uint32_t u;
    asm("cvt.rna.tf32.f32 %0, %1;" : "=r"(u) : "f"(f));
    return u;
}

__global__ __launch_bounds__(256, 2) void gemm_tc_kernel(
    const float* __restrict__ x, const float* __restrict__ W,
    __half* __restrict__ out, int nrows)
{
    __shared__ uint32_t xs[MT][KB + 4];     // tf32; stride 36 -> conflict-free frags
    __shared__ uint32_t ws[KB][FDIM + 8];   // tf32; stride 136 -> conflict-free frags

    int tid = threadIdx.x;
    int wid = tid >> 5;
    int lane = tid & 31;
    int m_base = (wid & 3) * 32;
    int n_base = (wid >> 2) * 64;
    int row0 = blockIdx.x * MT;

    float acc[2][8][4];
#pragma unroll
    for (int im = 0; im < 2; im++)
#pragma unroll
        for (int in = 0; in < 8; in++)
#pragma unroll
            for (int j = 0; j < 4; j++) acc[im][in][j] = 0.0f;

    int lr = tid >> 3;
    int lk = (tid & 7) * 4;
    int wk = tid >> 5;
    int wc = (tid & 31) * 4;

    for (int k0 = 0; k0 < FDIM; k0 += KB) {
#pragma unroll
        for (int p = 0; p < 4; p++) {
            int r = lr + p * 32;
            float4 v = make_float4(0.f, 0.f, 0.f, 0.f);
            if (row0 + r < nrows)
                v = *(const float4*)(x + (long long)(row0 + r) * FDIM + k0 + lk);
            xs[r][lk]     = f2tf32(v.x);
            xs[r][lk + 1] = f2tf32(v.y);
            xs[r][lk + 2] = f2tf32(v.z);
            xs[r][lk + 3] = f2tf32(v.w);
        }
#pragma unroll
        for (int p = 0; p < 4; p++) {
            int kk = wk + p * 8;
            float4 v = *(const float4*)(W + (long long)(k0 + kk) * FDIM + wc);
            ws[kk][wc]     = f2tf32(v.x);
            ws[kk][wc + 1] = f2tf32(v.y);
            ws[kk][wc + 2] = f2tf32(v.z);
            ws[kk][wc + 3] = f2tf32(v.w);
        }
        __syncthreads();

#pragma unroll
        for (int ks = 0; ks < KB / 8; ks++) {
            int kk = ks * 8;
            uint32_t a[2][4];
            int ac = kk + (lane & 3);
#pragma unroll
            for (int im = 0; im < 2; im++) {
                int r0 = m_base + im * 16 + (lane >> 2);
                a[im][0] = xs[r0][ac];
                a[im][1] = xs[r0 + 8][ac];
                a[im][2] = xs[r0][ac + 4];
                a[im][3] = xs[r0 + 8][ac + 4];
            }
#pragma unroll
            for (int in = 0; in < 8; in++) {
                int c = n_base + in * 8 + (lane >> 2);
                uint32_t b0 = ws[kk + (lane & 3)][c];
                uint32_t b1 = ws[kk + 4 + (lane & 3)][c];
#pragma unroll
                for (int im = 0; im < 2; im++) {
                    asm volatile(
                        "mma.sync.aligned.m16n8k8.row.col.f32.tf32.tf32.f32 "
                        "{%0,%1,%2,%3}, {%4,%5,%6,%7}, {%8,%9}, {%0,%1,%2,%3};"
                        : "+f"(acc[im][in][0]), "+f"(acc[im][in][1]),
                          "+f"(acc[im][in][2]), "+f"(acc[im][in][3])
                        : "r"(a[im][0]), "r"(a[im][1]), "r"(a[im][2]), "r"(a[im][3]),
                          "r"(b0), "r"(b1));
                }
            }
        }
        __syncthreads();
    }

    // epilogue -> fp16
#pragma unroll
    for (int im = 0; im < 2; im++) {
        int r = row0 + m_base + im * 16 + (lane >> 2);
#pragma unroll
        for (int in = 0; in < 8; in++) {
            int c = n_base + in * 8 + 2 * (lane & 3);
            if (r < nrows)
                *(__half2*)(out + (long long)r * FDIM + c) =
                    __floats2half2_rn(acc[im][in][0], acc[im][in][1]);
            if (r + 8 < nrows)
                *(__half2*)(out + (long long)(r + 8) * FDIM + c) =
                    __floats2half2_rn(acc[im][in][2], acc[im][in][3]);
        }
    }
}

// ---------------- aggregate: one warp per destination node, fp16 gathers ------
__global__ __launch_bounds__(256) void aggregate_kernel(
    const __half* __restrict__ xt, const int* __restrict__ rowptr,
    const int* __restrict__ cnt, const int* __restrict__ srcs,
    const float* __restrict__ dinv, const float* __restrict__ b,
    float* __restrict__ out, int n)
{
    int warp = (blockIdx.x * blockDim.x + threadIdx.x) >> 5;
    int lane = threadIdx.x & 31;
    if (warp >= n) return;

    float dc = __ldg(dinv + warp);
    float4 bb = *(const float4*)(b + lane * 4);
    uint2 sraw = *(const uint2*)(xt + (long long)warp * FDIM + lane * 4);
    float2 s01 = __half22float2(*(__half2*)&sraw.x);
    float2 s23 = __half22float2(*(__half2*)&sraw.y);
    float self = dc * dc;
    float4 acc;
    acc.x = fmaf(s01.x, self, bb.x);
    acc.y = fmaf(s01.y, self, bb.y);
    acc.z = fmaf(s23.x, self, bb.z);
    acc.w = fmaf(s23.y, self, bb.w);

    int k0 = __ldg(rowptr + warp);
    int k1 = k0 + __ldg(cnt + warp);
#pragma unroll 4
    for (int k = k0; k < k1; k++) {
        int s = __ldg(srcs + k);
        float norm = dc * __ldg(dinv + s);
        uint2 v = *(const uint2*)(xt + (long long)s * FDIM + lane * 4);
        float2 v01 = __half22float2(*(__half2*)&v.x);
        float2 v23 = __half22float2(*(__half2*)&v.y);
        acc.x = fmaf(v01.x, norm, acc.x);
        acc.y = fmaf(v01.y, norm, acc.y);
        acc.z = fmaf(v23.x, norm, acc.z);
        acc.w = fmaf(v23.y, norm, acc.w);
    }
    *(float4*)(out + (long long)warp * FDIM + lane * 4) = acc;
}

// ---------------- launch ----------------
extern "C" void kernel_launch(void* const* d_in, const int* in_sizes, int n_in,
                              void* d_out, int out_size)
{
    const float* node_feature = (const float*)d_in[0];
    const int*   edge_index   = (const int*)d_in[1];   // int32 (jax x64 disabled)
    const float* W1 = (const float*)d_in[2];
    const float* b1 = (const float*)d_in[3];
    const float* W2 = (const float*)d_in[4];
    const float* b2 = (const float*)d_in[5];
    float* out = (float*)d_out;

    int n = in_sizes[0] / FDIM;          // 100000
    int E = in_sizes[1] / 2;             // 1600000
    const int* rows = edge_index;
    const int* cols = edge_index + E;

    __half* xt;
    float *h1, *dinv;
    int *cnt, *rowptr, *cur, *srcs, *bsums;
    cudaGetSymbolAddress((void**)&xt,     g_xt);
    cudaGetSymbolAddress((void**)&h1,     g_h1);
    cudaGetSymbolAddress((void**)&dinv,   g_dinv);
    cudaGetSymbolAddress((void**)&cnt,    g_cnt);
    cudaGetSymbolAddress((void**)&rowptr, g_rowptr);
    cudaGetSymbolAddress((void**)&cur,    g_cur);
    cudaGetSymbolAddress((void**)&srcs,   g_src_sorted);
    cudaGetSymbolAddress((void**)&bsums,  g_bsums);

    int tb = 256;
    int nb_nodes = (n + tb - 1) / tb;
    int nb_edge4 = ((E >> 2) + tb - 1) / tb;
    int nb_gemm  = (n + MT - 1) / MT;
    int nb_scan  = (n + SCAN_BS - 1) / SCAN_BS;
    int nb_agg   = (n * 32 + tb - 1) / tb;

    // CSR build (shared by both layers)
    cnt_zero_kernel<<<nb_nodes, tb>>>(cnt, n);
    hist_kernel<<<nb_edge4, tb>>>(cols, cnt, E);
    dinv_kernel<<<nb_nodes, tb>>>(cnt, dinv, n);
    scan_block_kernel<<<nb_scan, SCAN_BS>>>(cnt, rowptr, bsums, n);
    scan_sums_kernel<<<1, SCAN_BS>>>(bsums, nb_scan);
    scan_add_cursor_kernel<<<nb_scan, SCAN_BS>>>(rowptr, bsums, cur, n);
    place_kernel<<<nb_edge4, tb>>>(rows, cols, cur, srcs, E);

    // layer 1
    gemm_tc_kernel<<<nb_gemm, tb>>>(node_feature, W1, xt, n);
    aggregate_kernel<<<nb_agg, tb>>>(xt, rowptr, cnt, srcs, dinv, b1, h1, n);

    // layer 2
    gemm_tc_kernel<<<nb_gemm, tb>>>(h1, W2, xt, n);
    aggregate_kernel<<<nb_agg, tb>>>(xt, rowptr, cnt, srcs, dinv, b2, out, n);
}